// round 3
// baseline (speedup 1.0000x reference)
#include <cuda_runtime.h>
#include <cstdint>
#include <math.h>

// ---------------------------------------------------------------------------
// Problem constants
// ---------------------------------------------------------------------------
namespace {
constexpr int NTOK = 8192;      // B*T = 4*2048
constexpr int CD   = 1024;      // C
constexpr int NE   = 8;         // experts
constexpr int HD   = 1408;      // expert intermediate
constexpr int HSD  = 2816;      // shared intermediate
constexpr int NPAIR = NTOK * 2; // top-2

constexpr int BM = 128, BN = 64, BK = 16, NTHREADS = 256;
}

// ---------------------------------------------------------------------------
// Scratch (allocation-free: __device__ globals)
// ---------------------------------------------------------------------------
__device__ int   g_counts[NE];
__device__ int   g_offsets[NE];
__device__ int   g_cursor[NE];
__device__ int   g_tok[NPAIR];
__device__ float g_gatew[NPAIR];
__device__ int   g_dest[NPAIR];
__device__ int   g_topi[NPAIR];
__device__ float g_topp[NPAIR];
__device__ float g_h [(size_t)NPAIR * HD];   // expert hidden (grouped by expert)
__device__ float g_hs[(size_t)NTOK * HSD];   // shared-expert hidden
__device__ float g_yp[(size_t)NPAIR * CD];   // per-pair expert outputs, slot 2t+k

// ---------------------------------------------------------------------------
// PTX helpers
// ---------------------------------------------------------------------------
__device__ __forceinline__ uint32_t f2tf(float f) {
    uint32_t u; asm("cvt.rna.tf32.f32 %0, %1;" : "=r"(u) : "f"(f)); return u;
}
__device__ __forceinline__ void mma8(float d[4], const uint32_t a[4],
                                     uint32_t b0, uint32_t b1) {
    asm volatile(
        "mma.sync.aligned.m16n8k8.row.col.f32.tf32.tf32.f32 "
        "{%0,%1,%2,%3},{%4,%5,%6,%7},{%8,%9},{%0,%1,%2,%3};"
        : "+f"(d[0]), "+f"(d[1]), "+f"(d[2]), "+f"(d[3])
        : "r"(a[0]), "r"(a[1]), "r"(a[2]), "r"(a[3]), "r"(b0), "r"(b1));
}
__device__ __forceinline__ void cp16(float* smem_dst, const float* gsrc) {
    uint32_t s = (uint32_t)__cvta_generic_to_shared(smem_dst);
    asm volatile("cp.async.cg.shared.global [%0], [%1], 16;" :: "r"(s), "l"(gsrc));
}
__device__ __forceinline__ float silu_mul(float g, float u) {
    return (g / (1.0f + expf(-g))) * u;
}

// ---------------------------------------------------------------------------
// Router: warp per token, logits = x @ Wg, top-2, softmax over the pair
// ---------------------------------------------------------------------------
__global__ void router_kernel(const float* __restrict__ x,
                              const float* __restrict__ Wg) {
    int warp = threadIdx.x >> 5, lane = threadIdx.x & 31;
    int t = blockIdx.x * 8 + warp;
    const float* xr = x + (size_t)t * CD;
    float acc[NE];
#pragma unroll
    for (int e = 0; e < NE; e++) acc[e] = 0.f;
    for (int c = lane; c < CD; c += 32) {
        float xv = __ldg(xr + c);
        const float4* wr = reinterpret_cast<const float4*>(Wg + c * NE);
        float4 w0 = wr[0], w1 = wr[1];
        acc[0] += xv * w0.x; acc[1] += xv * w0.y;
        acc[2] += xv * w0.z; acc[3] += xv * w0.w;
        acc[4] += xv * w1.x; acc[5] += xv * w1.y;
        acc[6] += xv * w1.z; acc[7] += xv * w1.w;
    }
#pragma unroll
    for (int off = 16; off > 0; off >>= 1)
#pragma unroll
        for (int e = 0; e < NE; e++)
            acc[e] += __shfl_xor_sync(0xffffffffu, acc[e], off);

    if (lane == 0) {
        int i0 = 0; float l0 = acc[0];
#pragma unroll
        for (int e = 1; e < NE; e++) if (acc[e] > l0) { l0 = acc[e]; i0 = e; }
        int i1 = (i0 == 0) ? 1 : 0; float l1 = acc[i1];
#pragma unroll
        for (int e = 0; e < NE; e++)
            if (e != i0 && acc[e] > l1) { l1 = acc[e]; i1 = e; }
        float ex = expf(l1 - l0);            // l0 >= l1
        float inv = 1.0f / (1.0f + ex);
        g_topi[2*t]   = i0;  g_topi[2*t+1] = i1;
        g_topp[2*t]   = inv; g_topp[2*t+1] = ex * inv;
        atomicAdd(&g_counts[i0], 1);
        atomicAdd(&g_counts[i1], 1);
    }
}

__global__ void zero_kernel() {
    if (threadIdx.x < NE) g_counts[threadIdx.x] = 0;
}

__global__ void offsets_kernel() {
    if (threadIdx.x == 0) {
        int s = 0;
        for (int e = 0; e < NE; e++) {
            g_offsets[e] = s; g_cursor[e] = s; s += g_counts[e];
        }
    }
}

__global__ void scatter_kernel() {
    int t = blockIdx.x * blockDim.x + threadIdx.x;
    if (t < NTOK) {
#pragma unroll
        for (int k = 0; k < 2; k++) {
            int e = g_topi[2*t + k];
            int pos = atomicAdd(&g_cursor[e], 1);
            g_tok[pos]   = t;
            g_gatew[pos] = g_topp[2*t + k];
            g_dest[pos]  = 2*t + k;
        }
    }
}

// ---------------------------------------------------------------------------
// MLP stage 1: H = silu(X @ W1) * (X @ W2)   (dual GEMM, fused epilogue)
// EXPERT: gathered rows per expert (blockIdx.z), output g_h grouped by expert.
// !EXPERT: shared expert over all tokens, output g_hs.
// ---------------------------------------------------------------------------
template<int KDIM, int NCOLS, bool EXPERT>
__global__ __launch_bounds__(NTHREADS)
void mlp1_kernel(const float* __restrict__ X,
                 const float* __restrict__ W1b,
                 const float* __restrict__ W2b) {
    __shared__ float As [2][BM][BK + 4];
    __shared__ float B1s[2][BK][BN + 8];
    __shared__ float B2s[2][BK][BN + 8];

    const int e   = EXPERT ? blockIdx.z : 0;
    const int M   = EXPERT ? g_counts[e]  : NTOK;
    const int off = EXPERT ? g_offsets[e] : 0;
    const int m0  = blockIdx.y * BM;
    if (m0 >= M) return;
    const int n0  = blockIdx.x * BN;

    const float* W1 = W1b + (size_t)e * KDIM * NCOLS;
    const float* W2 = W2b + (size_t)e * KDIM * NCOLS;
    float* Hout = EXPERT ? g_h : g_hs;

    const int tid = threadIdx.x;

    // A-tile loader setup: 512 16B chunks -> 2 per thread
    const float* arowp[2]; int ar[2], akp[2];
#pragma unroll
    for (int j = 0; j < 2; j++) {
        int chunk = tid + j * NTHREADS;
        ar[j]  = chunk >> 2;
        akp[j] = (chunk & 3) * 4;
        int m  = m0 + ar[j];
        int rr = (m < M) ? m : (M - 1);
        int row = EXPERT ? g_tok[off + rr] : rr;
        arowp[j] = X + (size_t)row * KDIM;
    }
    const int br = tid >> 4, bc = (tid & 15) * 4;
    const float* b1p = W1 + (size_t)br * NCOLS + n0 + bc;
    const float* b2p = W2 + (size_t)br * NCOLS + n0 + bc;

    auto load_stage = [&](int kt, int buf) {
        int k0 = kt * BK;
#pragma unroll
        for (int j = 0; j < 2; j++)
            cp16(&As[buf][ar[j]][akp[j]], arowp[j] + k0 + akp[j]);
        cp16(&B1s[buf][br][bc], b1p + (size_t)k0 * NCOLS);
        cp16(&B2s[buf][br][bc], b2p + (size_t)k0 * NCOLS);
        asm volatile("cp.async.commit_group;");
    };

    const int wid = tid >> 5, wm = wid & 3, wn = wid >> 2;
    const int lane = tid & 31, grp = lane >> 2, tig = lane & 3;
    float acc1[2][4][4] = {}; float acc2[2][4][4] = {};

    auto compute_stage = [&](int buf) {
#pragma unroll
        for (int ks = 0; ks < 2; ks++) {
            int kb = ks * 8;
            uint32_t a[2][4];
#pragma unroll
            for (int mt = 0; mt < 2; mt++) {
                int mr = wm * 32 + mt * 16;
                a[mt][0] = f2tf(As[buf][mr + grp    ][kb + tig    ]);
                a[mt][1] = f2tf(As[buf][mr + grp + 8][kb + tig    ]);
                a[mt][2] = f2tf(As[buf][mr + grp    ][kb + tig + 4]);
                a[mt][3] = f2tf(As[buf][mr + grp + 8][kb + tig + 4]);
            }
#pragma unroll
            for (int nt = 0; nt < 4; nt++) {
                int nc = wn * 32 + nt * 8 + grp;
                uint32_t b0 = f2tf(B1s[buf][kb + tig    ][nc]);
                uint32_t b1 = f2tf(B1s[buf][kb + tig + 4][nc]);
                mma8(acc1[0][nt], a[0], b0, b1);
                mma8(acc1[1][nt], a[1], b0, b1);
                uint32_t c0 = f2tf(B2s[buf][kb + tig    ][nc]);
                uint32_t c1 = f2tf(B2s[buf][kb + tig + 4][nc]);
                mma8(acc2[0][nt], a[0], c0, c1);
                mma8(acc2[1][nt], a[1], c0, c1);
            }
        }
    };

    load_stage(0, 0);
    const int KT = KDIM / BK;
    for (int kt = 0; kt < KT; ++kt) {
        int cur = kt & 1;
        if (kt + 1 < KT) {
            load_stage(kt + 1, cur ^ 1);
            asm volatile("cp.async.wait_group 1;");
        } else {
            asm volatile("cp.async.wait_group 0;");
        }
        __syncthreads();
        compute_stage(cur);
        __syncthreads();
    }

    // Epilogue: silu-gate, store
#pragma unroll
    for (int mt = 0; mt < 2; mt++) {
        int rb = m0 + wm * 32 + mt * 16 + grp;
#pragma unroll
        for (int half = 0; half < 2; half++) {
            int r = rb + half * 8;
            if (r < M) {
                size_t rowoff = (size_t)(off + r) * NCOLS;
#pragma unroll
                for (int nt = 0; nt < 4; nt++) {
                    int col = n0 + wn * 32 + nt * 8 + tig * 2;
                    float v0 = silu_mul(acc1[mt][nt][half*2+0], acc2[mt][nt][half*2+0]);
                    float v1 = silu_mul(acc1[mt][nt][half*2+1], acc2[mt][nt][half*2+1]);
                    *reinterpret_cast<float2*>(&Hout[rowoff + col]) = make_float2(v0, v1);
                }
            }
        }
    }
}

// ---------------------------------------------------------------------------
// MLP stage 2: Y = H @ W3 (single GEMM).
// EXPERT: rows from g_h, scaled by gate, scattered to g_yp[dest].
// !EXPERT: rows from g_hs, written straight into d_out.
// ---------------------------------------------------------------------------
template<int KDIM, bool EXPERT>
__global__ __launch_bounds__(NTHREADS)
void mlp2_kernel(const float* __restrict__ Wb, float* __restrict__ Out) {
    __shared__ float As[2][BM][BK + 4];
    __shared__ float Bs[2][BK][BN + 8];

    const int e   = EXPERT ? blockIdx.z : 0;
    const int M   = EXPERT ? g_counts[e]  : NTOK;
    const int off = EXPERT ? g_offsets[e] : 0;
    const int m0  = blockIdx.y * BM;
    if (m0 >= M) return;
    const int n0  = blockIdx.x * BN;

    const float* A = EXPERT ? g_h : g_hs;
    const float* W = Wb + (size_t)e * KDIM * CD;

    const int tid = threadIdx.x;
    const float* arowp[2]; int ar[2], akp[2];
#pragma unroll
    for (int j = 0; j < 2; j++) {
        int chunk = tid + j * NTHREADS;
        ar[j]  = chunk >> 2;
        akp[j] = (chunk & 3) * 4;
        int m  = m0 + ar[j];
        int rr = (m < M) ? m : (M - 1);
        arowp[j] = A + (size_t)(off + rr) * KDIM;
    }
    const int br = tid >> 4, bc = (tid & 15) * 4;
    const float* bp = W + (size_t)br * CD + n0 + bc;

    auto load_stage = [&](int kt, int buf) {
        int k0 = kt * BK;
#pragma unroll
        for (int j = 0; j < 2; j++)
            cp16(&As[buf][ar[j]][akp[j]], arowp[j] + k0 + akp[j]);
        cp16(&Bs[buf][br][bc], bp + (size_t)k0 * CD);
        asm volatile("cp.async.commit_group;");
    };

    const int wid = tid >> 5, wm = wid & 3, wn = wid >> 2;
    const int lane = tid & 31, grp = lane >> 2, tig = lane & 3;
    float acc[2][4][4] = {};

    auto compute_stage = [&](int buf) {
#pragma unroll
        for (int ks = 0; ks < 2; ks++) {
            int kb = ks * 8;
            uint32_t a[2][4];
#pragma unroll
            for (int mt = 0; mt < 2; mt++) {
                int mr = wm * 32 + mt * 16;
                a[mt][0] = f2tf(As[buf][mr + grp    ][kb + tig    ]);
                a[mt][1] = f2tf(As[buf][mr + grp + 8][kb + tig    ]);
                a[mt][2] = f2tf(As[buf][mr + grp    ][kb + tig + 4]);
                a[mt][3] = f2tf(As[buf][mr + grp + 8][kb + tig + 4]);
            }
#pragma unroll
            for (int nt = 0; nt < 4; nt++) {
                int nc = wn * 32 + nt * 8 + grp;
                uint32_t b0 = f2tf(Bs[buf][kb + tig    ][nc]);
                uint32_t b1 = f2tf(Bs[buf][kb + tig + 4][nc]);
                mma8(acc[0][nt], a[0], b0, b1);
                mma8(acc[1][nt], a[1], b0, b1);
            }
        }
    };

    load_stage(0, 0);
    const int KT = KDIM / BK;
    for (int kt = 0; kt < KT; ++kt) {
        int cur = kt & 1;
        if (kt + 1 < KT) {
            load_stage(kt + 1, cur ^ 1);
            asm volatile("cp.async.wait_group 1;");
        } else {
            asm volatile("cp.async.wait_group 0;");
        }
        __syncthreads();
        compute_stage(cur);
        __syncthreads();
    }

#pragma unroll
    for (int mt = 0; mt < 2; mt++) {
        int rb = m0 + wm * 32 + mt * 16 + grp;
#pragma unroll
        for (int half = 0; half < 2; half++) {
            int r = rb + half * 8;
            if (r < M) {
                float scale; float* dst;
                if (EXPERT) {
                    scale = g_gatew[off + r];
                    dst   = g_yp + (size_t)g_dest[off + r] * CD;
                } else {
                    scale = 1.0f;
                    dst   = Out + (size_t)r * CD;
                }
#pragma unroll
                for (int nt = 0; nt < 4; nt++) {
                    int col = n0 + wn * 32 + nt * 8 + tig * 2;
                    float v0 = acc[mt][nt][half*2+0] * scale;
                    float v1 = acc[mt][nt][half*2+1] * scale;
                    *reinterpret_cast<float2*>(&dst[col]) = make_float2(v0, v1);
                }
            }
        }
    }
}

// ---------------------------------------------------------------------------
// Final combine: out[t] += yp[2t] + yp[2t+1]  (shared-expert result already in out)
// ---------------------------------------------------------------------------
__global__ void combine_kernel(float* __restrict__ Out) {
    size_t i = (size_t)blockIdx.x * blockDim.x + threadIdx.x;   // over NTOK*CD/4
    size_t t  = i / (CD / 4);
    size_t c4 = i % (CD / 4);
    float4* o = reinterpret_cast<float4*>(Out) + t * (CD / 4) + c4;
    const float4* p0 = reinterpret_cast<const float4*>(g_yp) + (2 * t) * (CD / 4) + c4;
    const float4* p1 = p0 + (CD / 4);
    float4 a = *o, x0 = *p0, x1 = *p1;
    a.x += x0.x + x1.x; a.y += x0.y + x1.y;
    a.z += x0.z + x1.z; a.w += x0.w + x1.w;
    *o = a;
}

// ---------------------------------------------------------------------------
// Launch
// ---------------------------------------------------------------------------
extern "C" void kernel_launch(void* const* d_in, const int* in_sizes, int n_in,
                              void* d_out, int out_size) {
    const float* x   = (const float*)d_in[0];
    const float* Wg  = (const float*)d_in[1];
    const float* W1  = (const float*)d_in[2];
    const float* W2  = (const float*)d_in[3];
    const float* W3  = (const float*)d_in[4];
    const float* Ws1 = (const float*)d_in[5];
    const float* Ws2 = (const float*)d_in[6];
    const float* Ws3 = (const float*)d_in[7];
    float* out = (float*)d_out;

    zero_kernel<<<1, 32>>>();
    router_kernel<<<NTOK / 8, 256>>>(x, Wg);
    offsets_kernel<<<1, 32>>>();
    scatter_kernel<<<NTOK / 256, 256>>>();

    // Expert stage 1: h = silu(x@W1)*(x@W2) per routed token
    mlp1_kernel<CD, HD, true><<<dim3(HD / BN, NTOK / BM, NE), NTHREADS>>>(x, W1, W2);
    // Shared stage 1
    mlp1_kernel<CD, HSD, false><<<dim3(HSD / BN, NTOK / BM, 1), NTHREADS>>>(x, Ws1, Ws2);
    // Shared stage 2 -> writes d_out directly
    mlp2_kernel<HSD, false><<<dim3(CD / BN, NTOK / BM, 1), NTHREADS>>>(Ws3, out);
    // Expert stage 2 -> g_yp (gate-scaled, deterministic slots)
    mlp2_kernel<HD, true><<<dim3(CD / BN, NTOK / BM, NE), NTHREADS>>>(W3, out);
    // Combine
    combine_kernel<<<(NTOK * CD / 4) / 256, 256>>>(out);
}

// round 9
// speedup vs baseline: 1.0204x; 1.0204x over previous
#include <cuda_runtime.h>
#include <cstdint>
#include <math.h>

// ---------------------------------------------------------------------------
// Problem constants
// ---------------------------------------------------------------------------
namespace {
constexpr int NTOK = 8192;      // B*T
constexpr int CD   = 1024;      // C
constexpr int NE   = 8;
constexpr int HD   = 1408;
constexpr int HSD  = 2816;
constexpr int NPAIR = NTOK * 2;

// GEMM tiling (round-1 proven skeleton, widened)
constexpr int BM = 128, BN = 128, BK = 16, NTHR = 256;
}

// ---------------------------------------------------------------------------
// Scratch (allocation-free: __device__ globals; referenced ONLY in device code)
// ---------------------------------------------------------------------------
__device__ int   g_counts[NE];
__device__ int   g_offsets[NE];
__device__ int   g_cursor[NE];
__device__ int   g_tok[NPAIR];
__device__ float g_gatew[NPAIR];
__device__ int   g_dest[NPAIR];
__device__ int   g_topi[NPAIR];
__device__ float g_topp[NPAIR];

__device__ float g_xr  [(size_t)NTOK * CD];          // tf32-rounded x
__device__ float g_w12c[(size_t)NE * CD * (2*HD)];   // [e][k][W1|W2] rounded
__device__ float g_ws12[(size_t)CD * (2*HSD)];       // [k][Ws1|Ws2] rounded
__device__ float g_w3r [(size_t)NE * HD * CD];       // rounded
__device__ float g_ws3r[(size_t)HSD * CD];           // rounded
__device__ float g_h12 [(size_t)NPAIR * 2*HD];       // pre-silu expert hidden
__device__ float g_hs12[(size_t)NTOK * 2*HSD];       // pre-silu shared hidden
__device__ float g_h   [(size_t)NPAIR * HD];         // gated expert hidden (rounded)
__device__ float g_hs  [(size_t)NTOK * HSD];         // gated shared hidden (rounded)
__device__ float g_yp  [(size_t)NPAIR * CD];         // per-pair expert outputs

// ---------------------------------------------------------------------------
// Helpers
// ---------------------------------------------------------------------------
__device__ __forceinline__ float tf32r(float f) {
    uint32_t u; asm("cvt.rna.tf32.f32 %0, %1;" : "=r"(u) : "f"(f));
    return __uint_as_float(u);
}
__device__ __forceinline__ float silu_mul(float g, float u) {
    return (g / (1.0f + expf(-g))) * u;
}
__device__ __forceinline__ void mma8(float d[4], const uint32_t a[4],
                                     uint32_t b0, uint32_t b1) {
    asm volatile(
        "mma.sync.aligned.m16n8k8.row.col.f32.tf32.tf32.f32 "
        "{%0,%1,%2,%3},{%4,%5,%6,%7},{%8,%9},{%0,%1,%2,%3};"
        : "+f"(d[0]), "+f"(d[1]), "+f"(d[2]), "+f"(d[3])
        : "r"(a[0]), "r"(a[1]), "r"(a[2]), "r"(a[3]), "r"(b0), "r"(b1));
}
__device__ __forceinline__ void cp16(float* smem_dst, const float* gsrc) {
    uint32_t s = (uint32_t)__cvta_generic_to_shared(smem_dst);
    asm volatile("cp.async.cg.shared.global [%0], [%1], 16;" :: "r"(s), "l"(gsrc));
}

// ---------------------------------------------------------------------------
// Router / routing bookkeeping (proven round-1 code)
// ---------------------------------------------------------------------------
__global__ void router_kernel(const float* __restrict__ x,
                              const float* __restrict__ Wg) {
    int warp = threadIdx.x >> 5, lane = threadIdx.x & 31;
    int t = blockIdx.x * 8 + warp;
    const float* xr = x + (size_t)t * CD;
    float acc[NE];
#pragma unroll
    for (int e = 0; e < NE; e++) acc[e] = 0.f;
    for (int c = lane; c < CD; c += 32) {
        float xv = __ldg(xr + c);
        const float4* wr = reinterpret_cast<const float4*>(Wg + c * NE);
        float4 w0 = wr[0], w1 = wr[1];
        acc[0] += xv * w0.x; acc[1] += xv * w0.y;
        acc[2] += xv * w0.z; acc[3] += xv * w0.w;
        acc[4] += xv * w1.x; acc[5] += xv * w1.y;
        acc[6] += xv * w1.z; acc[7] += xv * w1.w;
    }
#pragma unroll
    for (int off = 16; off > 0; off >>= 1)
#pragma unroll
        for (int e = 0; e < NE; e++)
            acc[e] += __shfl_xor_sync(0xffffffffu, acc[e], off);

    if (lane == 0) {
        int i0 = 0; float l0 = acc[0];
#pragma unroll
        for (int e = 1; e < NE; e++) if (acc[e] > l0) { l0 = acc[e]; i0 = e; }
        int i1 = (i0 == 0) ? 1 : 0; float l1 = acc[i1];
#pragma unroll
        for (int e = 0; e < NE; e++)
            if (e != i0 && acc[e] > l1) { l1 = acc[e]; i1 = e; }
        float ex = expf(l1 - l0);
        float inv = 1.0f / (1.0f + ex);
        g_topi[2*t]   = i0;  g_topi[2*t+1] = i1;
        g_topp[2*t]   = inv; g_topp[2*t+1] = ex * inv;
        atomicAdd(&g_counts[i0], 1);
        atomicAdd(&g_counts[i1], 1);
    }
}

__global__ void zero_kernel() {
    if (threadIdx.x < NE) g_counts[threadIdx.x] = 0;
}
__global__ void offsets_kernel() {
    if (threadIdx.x == 0) {
        int s = 0;
        for (int e = 0; e < NE; e++) { g_offsets[e] = s; g_cursor[e] = s; s += g_counts[e]; }
    }
}
__global__ void scatter_kernel() {
    int t = blockIdx.x * blockDim.x + threadIdx.x;
    if (t < NTOK) {
#pragma unroll
        for (int k = 0; k < 2; k++) {
            int e = g_topi[2*t + k];
            int pos = atomicAdd(&g_cursor[e], 1);
            g_tok[pos]   = t;
            g_gatew[pos] = g_topp[2*t + k];
            g_dest[pos]  = 2*t + k;
        }
    }
}

// ---------------------------------------------------------------------------
// Pre-rounding copies (tf32 RNA once; GEMMs then load raw bits)
// All scratch destinations resolved in DEVICE code via template IDs.
// ---------------------------------------------------------------------------
__global__ void roundx_kernel(const float* __restrict__ x) {
    size_t i = (size_t)blockIdx.x * blockDim.x + threadIdx.x;
    float4 v = reinterpret_cast<const float4*>(x)[i];
    v.x = tf32r(v.x); v.y = tf32r(v.y); v.z = tf32r(v.z); v.w = tf32r(v.w);
    reinterpret_cast<float4*>(g_xr)[i] = v;
}

// DSTID 0 -> g_w12c (H=HD), DSTID 1 -> g_ws12 (H=HSD)
template<int H, int DSTID>
__global__ void concat_round_kernel(const float* __restrict__ W1,
                                    const float* __restrict__ W2) {
    float* dst = (DSTID == 0) ? g_w12c : g_ws12;
    size_t i = (size_t)blockIdx.x * blockDim.x + threadIdx.x;   // over R*H/4
    constexpr int h4 = H / 4;
    size_t r = i / h4, j = i % h4;
    float4 a = reinterpret_cast<const float4*>(W1)[r * h4 + j];
    float4 b = reinterpret_cast<const float4*>(W2)[r * h4 + j];
    a.x = tf32r(a.x); a.y = tf32r(a.y); a.z = tf32r(a.z); a.w = tf32r(a.w);
    b.x = tf32r(b.x); b.y = tf32r(b.y); b.z = tf32r(b.z); b.w = tf32r(b.w);
    reinterpret_cast<float4*>(dst)[r * (2 * h4) + j] = a;
    reinterpret_cast<float4*>(dst)[r * (2 * h4) + h4 + j] = b;
}

// DSTID 0 -> g_w3r, DSTID 1 -> g_ws3r
template<int DSTID>
__global__ void round_copy_kernel(const float* __restrict__ src) {
    float* dst = (DSTID == 0) ? g_w3r : g_ws3r;
    size_t i = (size_t)blockIdx.x * blockDim.x + threadIdx.x;
    float4 v = reinterpret_cast<const float4*>(src)[i];
    v.x = tf32r(v.x); v.y = tf32r(v.y); v.z = tf32r(v.z); v.w = tf32r(v.w);
    reinterpret_cast<float4*>(dst)[i] = v;
}

// ---------------------------------------------------------------------------
// silu combine: hout[r][c] = rnd( silu(h12[r][c]) * h12[r][H+c] )
// H==HD -> g_h12 -> g_h ; H==HSD -> g_hs12 -> g_hs
// ---------------------------------------------------------------------------
template<int H>
__global__ void silu_kernel() {
    const float* h12 = (H == HD) ? g_h12 : g_hs12;
    float*       hout = (H == HD) ? g_h  : g_hs;
    size_t i = (size_t)blockIdx.x * blockDim.x + threadIdx.x;   // rows*H/4
    constexpr int h4 = H / 4;
    size_t r = i / h4, j = i % h4;
    float4 g = reinterpret_cast<const float4*>(h12)[r * (2 * h4) + j];
    float4 u = reinterpret_cast<const float4*>(h12)[r * (2 * h4) + h4 + j];
    float4 o;
    o.x = tf32r(silu_mul(g.x, u.x));
    o.y = tf32r(silu_mul(g.y, u.y));
    o.z = tf32r(silu_mul(g.z, u.z));
    o.w = tf32r(silu_mul(g.w, u.w));
    reinterpret_cast<float4*>(hout)[r * h4 + j] = o;
}

// ---------------------------------------------------------------------------
// Unified GEMM: C[M-tile][N-tile] = A[M][KDIM] @ B[KDIM][NFULL]
// MODE 0: A = g_xr gathered via g_tok, B = g_w12c -> g_h12
// MODE 1: A = g_xr direct,            B = g_ws12 -> g_hs12
// MODE 2: A = g_h grouped,            B = g_w3r  -> g_yp (gate-scaled)
// MODE 3: A = g_hs direct,            B = g_ws3r -> Out
// BM=128, BN=128, BK=16, 256 threads, 8 warps (4m x 2n), warptile 32x64.
// Static smem: 2*(128*20 + 16*136)*4 = 37888 B.
// ---------------------------------------------------------------------------
template<int KDIM, int NFULL, int MODE>
__global__ __launch_bounds__(NTHR)
void gemm_tc(float* __restrict__ Out) {
    __shared__ float As[2][BM][BK + 4];
    __shared__ float Bs[2][BK][BN + 8];

    // Scratch pointers resolved in device code (constexpr select).
    const float* Bglob = (MODE == 0) ? g_w12c
                       : (MODE == 1) ? g_ws12
                       : (MODE == 2) ? g_w3r
                                     : g_ws3r;

    const int e   = (MODE == 0 || MODE == 2) ? blockIdx.z : 0;
    const int M   = (MODE == 0 || MODE == 2) ? g_counts[e]  : NTOK;
    const int off = (MODE == 0 || MODE == 2) ? g_offsets[e] : 0;
    const int m0  = blockIdx.y * BM;
    if (m0 >= M) return;
    const int n0  = blockIdx.x * BN;

    const float* B = Bglob + (size_t)e * KDIM * NFULL;
    const int tid = threadIdx.x;

    // A loader: 512 chunks of 16B -> 2 per thread
    int ar[2], ac4[2]; const float* ap[2];
#pragma unroll
    for (int j = 0; j < 2; j++) {
        int chunk = tid + j * NTHR;
        ar[j]  = chunk >> 2;                   // 0..127
        ac4[j] = (chunk & 3) * 4;              // {0,4,8,12}
        int rr = m0 + ar[j]; if (rr >= M) rr = M - 1;
        if (MODE == 0)      ap[j] = g_xr + (size_t)g_tok[off + rr] * KDIM + ac4[j];
        else if (MODE == 1) ap[j] = g_xr + (size_t)rr * KDIM + ac4[j];
        else if (MODE == 2) ap[j] = g_h  + (size_t)(off + rr) * KDIM + ac4[j];
        else                ap[j] = g_hs + (size_t)rr * KDIM + ac4[j];
    }
    // B loader: 16 rows x 32 chunks = 512 chunks -> 2 per thread
    int brr[2], bc4[2]; const float* bp[2];
#pragma unroll
    for (int j = 0; j < 2; j++) {
        int chunk = tid + j * NTHR;
        brr[j] = chunk >> 5;                   // 0..15
        bc4[j] = (chunk & 31) * 4;             // 0..124
        bp[j]  = B + (size_t)brr[j] * NFULL + n0 + bc4[j];
    }

    auto load_stage = [&](int kt, int buf) {
        int k0 = kt * BK;
#pragma unroll
        for (int j = 0; j < 2; j++)
            cp16(&As[buf][ar[j]][ac4[j]], ap[j] + k0);
#pragma unroll
        for (int j = 0; j < 2; j++)
            cp16(&Bs[buf][brr[j]][bc4[j]], bp[j] + (size_t)k0 * NFULL);
        asm volatile("cp.async.commit_group;");
    };

    const int wid = tid >> 5, wm = wid & 3, wn = wid >> 2;   // 4m x 2n warps
    const int lane = tid & 31, grp = lane >> 2, tig = lane & 3;
    float acc[2][8][4] = {};                                  // [mt][nt][4]

    auto compute_stage = [&](int buf) {
        const uint32_t* Au = reinterpret_cast<const uint32_t*>(&As[buf][0][0]);
        const uint32_t* Bu = reinterpret_cast<const uint32_t*>(&Bs[buf][0][0]);
#pragma unroll
        for (int ks = 0; ks < 2; ks++) {
            int kb = ks * 8;
            uint32_t a[2][4];
#pragma unroll
            for (int mt = 0; mt < 2; mt++) {
                int mr = wm * 32 + mt * 16;
                a[mt][0] = Au[(mr + grp    ) * (BK + 4) + kb + tig    ];
                a[mt][1] = Au[(mr + grp + 8) * (BK + 4) + kb + tig    ];
                a[mt][2] = Au[(mr + grp    ) * (BK + 4) + kb + tig + 4];
                a[mt][3] = Au[(mr + grp + 8) * (BK + 4) + kb + tig + 4];
            }
#pragma unroll
            for (int nt = 0; nt < 8; nt++) {
                int nc = wn * 64 + nt * 8 + grp;
                uint32_t b0 = Bu[(kb + tig    ) * (BN + 8) + nc];
                uint32_t b1 = Bu[(kb + tig + 4) * (BN + 8) + nc];
                mma8(acc[0][nt], a[0], b0, b1);
                mma8(acc[1][nt], a[1], b0, b1);
            }
        }
    };

    // Proven round-1 pipeline: 2-stage double buffer, sync-bracketed compute.
    load_stage(0, 0);
    constexpr int KT = KDIM / BK;
#pragma unroll 1
    for (int kt = 0; kt < KT; ++kt) {
        int cur = kt & 1;
        if (kt + 1 < KT) {
            load_stage(kt + 1, cur ^ 1);
            asm volatile("cp.async.wait_group 1;");
        } else {
            asm volatile("cp.async.wait_group 0;");
        }
        __syncthreads();
        compute_stage(cur);
        __syncthreads();
    }

    // Epilogue (scratch destinations resolved in device code)
#pragma unroll
    for (int mt = 0; mt < 2; mt++) {
        int rb = wm * 32 + mt * 16 + grp;
#pragma unroll
        for (int half = 0; half < 2; half++) {
            int r = m0 + rb + half * 8;
            if (r < M) {
                float scale = 1.0f; float* dst;
                if (MODE == 0)      dst = g_h12  + (size_t)(off + r) * (2*HD)  + n0;
                else if (MODE == 1) dst = g_hs12 + (size_t)r * (2*HSD) + n0;
                else if (MODE == 2) {
                    scale = g_gatew[off + r];
                    dst   = g_yp + (size_t)g_dest[off + r] * CD + n0;
                } else              dst = Out + (size_t)r * CD + n0;
#pragma unroll
                for (int nt = 0; nt < 8; nt++) {
                    int col = wn * 64 + nt * 8 + tig * 2;
                    float v0 = acc[mt][nt][half*2+0] * scale;
                    float v1 = acc[mt][nt][half*2+1] * scale;
                    *reinterpret_cast<float2*>(&dst[col]) = make_float2(v0, v1);
                }
            }
        }
    }
}

// ---------------------------------------------------------------------------
// Final combine: out[t] += yp[2t] + yp[2t+1]
// ---------------------------------------------------------------------------
__global__ void combine_kernel(float* __restrict__ Out) {
    size_t i = (size_t)blockIdx.x * blockDim.x + threadIdx.x;
    size_t t  = i / (CD / 4);
    size_t c4 = i % (CD / 4);
    float4* o = reinterpret_cast<float4*>(Out) + t * (CD / 4) + c4;
    const float4* p0 = reinterpret_cast<const float4*>(g_yp) + (2 * t) * (CD / 4) + c4;
    const float4* p1 = p0 + (CD / 4);
    float4 a = *o, x0 = *p0, x1 = *p1;
    a.x += x0.x + x1.x; a.y += x0.y + x1.y;
    a.z += x0.z + x1.z; a.w += x0.w + x1.w;
    *o = a;
}

// ---------------------------------------------------------------------------
// Launch — only harness pointers cross the host/device boundary.
// ---------------------------------------------------------------------------
extern "C" void kernel_launch(void* const* d_in, const int* in_sizes, int n_in,
                              void* d_out, int out_size) {
    const float* x   = (const float*)d_in[0];
    const float* Wg  = (const float*)d_in[1];
    const float* W1  = (const float*)d_in[2];
    const float* W2  = (const float*)d_in[3];
    const float* W3  = (const float*)d_in[4];
    const float* Ws1 = (const float*)d_in[5];
    const float* Ws2 = (const float*)d_in[6];
    const float* Ws3 = (const float*)d_in[7];
    float* out = (float*)d_out;

    // routing
    zero_kernel<<<1, 32>>>();
    router_kernel<<<NTOK / 8, 256>>>(x, Wg);
    offsets_kernel<<<1, 32>>>();
    scatter_kernel<<<NTOK / 256, 256>>>();

    // pre-round operands (tf32 RNA; idempotent under HMMA truncation)
    roundx_kernel<<<(NTOK * CD / 4) / 256, 256>>>(x);
    concat_round_kernel<HD,  0><<<(NE * CD * HD / 4) / 256, 256>>>(W1, W2);
    concat_round_kernel<HSD, 1><<<(CD * HSD / 4) / 256, 256>>>(Ws1, Ws2);
    round_copy_kernel<0><<<((size_t)NE * HD * CD / 4) / 256, 256>>>(W3);
    round_copy_kernel<1><<<((size_t)HSD * CD / 4) / 256, 256>>>(Ws3);

    // stage 1 GEMMs (concatenated [W1|W2]); 64 m-tiles worst case
    gemm_tc<CD, 2*HD,  0><<<dim3(2*HD  / BN, NTOK / BM, NE), NTHR>>>(out);
    gemm_tc<CD, 2*HSD, 1><<<dim3(2*HSD / BN, NTOK / BM, 1),  NTHR>>>(out);

    // silu-gate combine (also tf32-rounds the stage-2 A operand)
    silu_kernel<HD ><<<((size_t)NPAIR * HD  / 4) / 256, 256>>>();
    silu_kernel<HSD><<<((size_t)NTOK  * HSD / 4) / 256, 256>>>();

    // stage 2 GEMMs
    gemm_tc<HSD, CD, 3><<<dim3(CD / BN, NTOK / BM, 1),  NTHR>>>(out);
    gemm_tc<HD,  CD, 2><<<dim3(CD / BN, NTOK / BM, NE), NTHR>>>(out);

    // combine
    combine_kernel<<<(NTOK * CD / 4) / 256, 256>>>(out);
}

// round 10
// speedup vs baseline: 1.7499x; 1.7150x over previous
#include <cuda_runtime.h>
#include <cuda_fp16.h>
#include <cstdint>
#include <math.h>

// ---------------------------------------------------------------------------
// Problem constants
// ---------------------------------------------------------------------------
namespace {
constexpr int NTOK = 8192;      // B*T
constexpr int CD   = 1024;      // C
constexpr int NE   = 8;
constexpr int HD   = 1408;
constexpr int HSD  = 2816;
constexpr int NPAIR = NTOK * 2;

// GEMM tiling: fp16 m16n8k16, BK=32 (2 k-steps)
constexpr int BM = 128, BN = 128, BK = 32, NTHR = 256;
constexpr int SPAD = 8;                     // halves of row padding
constexpr int SSTR = BK + SPAD;             // 40 halves -> 20 uint32, conflict-free
}

// ---------------------------------------------------------------------------
// Scratch (allocation-free __device__ globals; referenced ONLY in device code)
// ---------------------------------------------------------------------------
__device__ int    g_counts[NE];
__device__ int    g_offsets[NE];
__device__ int    g_cursor[NE];
__device__ int    g_tok[NPAIR];
__device__ float  g_gatew[NPAIR];
__device__ int    g_dest[NPAIR];
__device__ int    g_topi[NPAIR];
__device__ float  g_topp[NPAIR];

__device__ __half g_xh  [(size_t)NTOK * CD];          // half x
__device__ __half g_w12i[(size_t)NE * (2*HD) * CD];   // [e][2c+{0,1}][k]: interleaved W1/W2, transposed
__device__ __half g_ws12[(size_t)(2*HSD) * CD];       // interleaved Ws1/Ws2, transposed
__device__ __half g_w3t [(size_t)NE * CD * HD];       // W3 transposed [n][k]
__device__ __half g_ws3t[(size_t)CD * HSD];           // Ws3 transposed
__device__ __half g_hh  [(size_t)NPAIR * HD];         // gated expert hidden (half)
__device__ __half g_hsh [(size_t)NTOK * HSD];         // gated shared hidden (half)
__device__ float  g_yp  [(size_t)NPAIR * CD];         // per-pair expert outputs (fp32)

// ---------------------------------------------------------------------------
// Helpers
// ---------------------------------------------------------------------------
__device__ __forceinline__ float silu_mul(float g, float u) {
    return (g / (1.0f + expf(-g))) * u;
}
__device__ __forceinline__ void mma16(float d[4], const uint32_t a[4],
                                      uint32_t b0, uint32_t b1) {
    asm volatile(
        "mma.sync.aligned.m16n8k16.row.col.f32.f16.f16.f32 "
        "{%0,%1,%2,%3},{%4,%5,%6,%7},{%8,%9},{%0,%1,%2,%3};"
        : "+f"(d[0]), "+f"(d[1]), "+f"(d[2]), "+f"(d[3])
        : "r"(a[0]), "r"(a[1]), "r"(a[2]), "r"(a[3]), "r"(b0), "r"(b1));
}
__device__ __forceinline__ void cp16h(__half* smem_dst, const __half* gsrc) {
    uint32_t s = (uint32_t)__cvta_generic_to_shared(smem_dst);
    asm volatile("cp.async.cg.shared.global [%0], [%1], 16;" :: "r"(s), "l"(gsrc));
}

// ---------------------------------------------------------------------------
// Router / routing bookkeeping (proven code)
// ---------------------------------------------------------------------------
__global__ void router_kernel(const float* __restrict__ x,
                              const float* __restrict__ Wg) {
    int warp = threadIdx.x >> 5, lane = threadIdx.x & 31;
    int t = blockIdx.x * 8 + warp;
    const float* xr = x + (size_t)t * CD;
    float acc[NE];
#pragma unroll
    for (int e = 0; e < NE; e++) acc[e] = 0.f;
    for (int c = lane; c < CD; c += 32) {
        float xv = __ldg(xr + c);
        const float4* wr = reinterpret_cast<const float4*>(Wg + c * NE);
        float4 w0 = wr[0], w1 = wr[1];
        acc[0] += xv * w0.x; acc[1] += xv * w0.y;
        acc[2] += xv * w0.z; acc[3] += xv * w0.w;
        acc[4] += xv * w1.x; acc[5] += xv * w1.y;
        acc[6] += xv * w1.z; acc[7] += xv * w1.w;
    }
#pragma unroll
    for (int off = 16; off > 0; off >>= 1)
#pragma unroll
        for (int e = 0; e < NE; e++)
            acc[e] += __shfl_xor_sync(0xffffffffu, acc[e], off);

    if (lane == 0) {
        int i0 = 0; float l0 = acc[0];
#pragma unroll
        for (int e = 1; e < NE; e++) if (acc[e] > l0) { l0 = acc[e]; i0 = e; }
        int i1 = (i0 == 0) ? 1 : 0; float l1 = acc[i1];
#pragma unroll
        for (int e = 0; e < NE; e++)
            if (e != i0 && acc[e] > l1) { l1 = acc[e]; i1 = e; }
        float ex = expf(l1 - l0);
        float inv = 1.0f / (1.0f + ex);
        g_topi[2*t]   = i0;  g_topi[2*t+1] = i1;
        g_topp[2*t]   = inv; g_topp[2*t+1] = ex * inv;
        atomicAdd(&g_counts[i0], 1);
        atomicAdd(&g_counts[i1], 1);
    }
}

__global__ void zero_kernel() {
    if (threadIdx.x < NE) g_counts[threadIdx.x] = 0;
}
__global__ void offsets_kernel() {
    if (threadIdx.x == 0) {
        int s = 0;
        for (int e = 0; e < NE; e++) { g_offsets[e] = s; g_cursor[e] = s; s += g_counts[e]; }
    }
}
__global__ void scatter_kernel() {
    int t = blockIdx.x * blockDim.x + threadIdx.x;
    if (t < NTOK) {
#pragma unroll
        for (int k = 0; k < 2; k++) {
            int e = g_topi[2*t + k];
            int pos = atomicAdd(&g_cursor[e], 1);
            g_tok[pos]   = t;
            g_gatew[pos] = g_topp[2*t + k];
            g_dest[pos]  = 2*t + k;
        }
    }
}

// ---------------------------------------------------------------------------
// x -> half
// ---------------------------------------------------------------------------
__global__ void halfx_kernel(const float* __restrict__ x) {
    size_t i = (size_t)blockIdx.x * blockDim.x + threadIdx.x;   // over N*C/4
    float4 v = reinterpret_cast<const float4*>(x)[i];
    __half2* d = reinterpret_cast<__half2*>(g_xh) + i * 2;
    d[0] = __floats2half2_rn(v.x, v.y);
    d[1] = __floats2half2_rn(v.z, v.w);
}

// ---------------------------------------------------------------------------
// Transpose + convert: src [z][R][C] fp32 -> dst rows oc = c*OS + OO, dst[z][oc][R] half
// DSTID: 0 g_w12i, 1 g_ws12, 2 g_w3t, 3 g_ws3t
// ---------------------------------------------------------------------------
template<int DSTID, int OS, int OO>
__global__ void transpose_half_kernel(const float* __restrict__ src,
                                      int R, int C,
                                      size_t in_bstride, size_t out_bstride) {
    __shared__ float t[32][33];
    __half* dstb = (DSTID == 0) ? g_w12i
                 : (DSTID == 1) ? g_ws12
                 : (DSTID == 2) ? g_w3t
                                : g_ws3t;
    const float* ip = src + (size_t)blockIdx.z * in_bstride;
    __half* op = dstb + (size_t)blockIdx.z * out_bstride;
    int c0 = blockIdx.x * 32, r0 = blockIdx.y * 32;
    int tx = threadIdx.x, ty = threadIdx.y;
#pragma unroll
    for (int j = 0; j < 4; j++)
        t[ty + 8*j][tx] = ip[(size_t)(r0 + ty + 8*j) * C + c0 + tx];
    __syncthreads();
#pragma unroll
    for (int j = 0; j < 4; j++) {
        int oc = (c0 + ty + 8*j) * OS + OO;
        op[(size_t)oc * R + r0 + tx] = __float2half_rn(t[tx][ty + 8*j]);
    }
}

// ---------------------------------------------------------------------------
// Unified fp16 GEMM: C = A[M][KDIM] @ Bt[NROWS][KDIM]^T
// MODE 0: A = g_xh gathered via g_tok, B = g_w12i[e] -> silu-fused -> g_hh
// MODE 1: A = g_xh direct,             B = g_ws12    -> silu-fused -> g_hsh
// MODE 2: A = g_hh grouped,            B = g_w3t[e]  -> g_yp (gate-scaled)
// MODE 3: A = g_hsh direct,            B = g_ws3t    -> Out
// BM=128, BN=128 (B rows), BK=32, 256 thr, 8 warps (4m x 2n), warptile 32x64.
// Static smem: 2*2*(128*40)*2B = 40960 B.
// ---------------------------------------------------------------------------
template<int KDIM, int NROWS, int MODE>
__global__ __launch_bounds__(NTHR)
void gemm_fp16(float* __restrict__ Out) {
    __shared__ __align__(16) __half As[2][BM][SSTR];
    __shared__ __align__(16) __half Bs[2][BN][SSTR];

    const __half* Bt = (MODE == 0) ? g_w12i
                     : (MODE == 1) ? g_ws12
                     : (MODE == 2) ? g_w3t
                                   : g_ws3t;

    const int e   = (MODE == 0 || MODE == 2) ? blockIdx.z : 0;
    const int M   = (MODE == 0 || MODE == 2) ? g_counts[e]  : NTOK;
    const int off = (MODE == 0 || MODE == 2) ? g_offsets[e] : 0;
    const int m0  = blockIdx.y * BM;
    if (m0 >= M) return;
    const int n0  = blockIdx.x * BN;

    const __half* B = Bt + (size_t)e * NROWS * KDIM;
    const int tid = threadIdx.x;

    // A loader: 128 rows x 4 chunks(16B=8 halves) = 512 chunks -> 2/thread
    int ar[2], ac8[2]; const __half* ap[2];
#pragma unroll
    for (int j = 0; j < 2; j++) {
        int chunk = tid + j * NTHR;
        ar[j]  = chunk >> 2;                   // 0..127
        ac8[j] = (chunk & 3) * 8;              // {0,8,16,24}
        int rr = m0 + ar[j]; if (rr >= M) rr = M - 1;
        if (MODE == 0)      ap[j] = g_xh + (size_t)g_tok[off + rr] * KDIM + ac8[j];
        else if (MODE == 1) ap[j] = g_xh + (size_t)rr * KDIM + ac8[j];
        else if (MODE == 2) ap[j] = g_hh + (size_t)(off + rr) * KDIM + ac8[j];
        else                ap[j] = g_hsh + (size_t)rr * KDIM + ac8[j];
    }
    // B loader: 128 B-rows x 4 chunks -> 512 chunks -> 2/thread
    int brr[2], bc8[2]; const __half* bp[2];
#pragma unroll
    for (int j = 0; j < 2; j++) {
        int chunk = tid + j * NTHR;
        brr[j] = chunk >> 2;
        bc8[j] = (chunk & 3) * 8;
        bp[j]  = B + (size_t)(n0 + brr[j]) * KDIM + bc8[j];
    }

    auto load_stage = [&](int kt, int buf) {
        int k0 = kt * BK;
#pragma unroll
        for (int j = 0; j < 2; j++)
            cp16h(&As[buf][ar[j]][ac8[j]], ap[j] + k0);
#pragma unroll
        for (int j = 0; j < 2; j++)
            cp16h(&Bs[buf][brr[j]][bc8[j]], bp[j] + k0);
        asm volatile("cp.async.commit_group;");
    };

    const int wid = tid >> 5, wm = wid & 3, wn = wid >> 2;   // 4m x 2n warps
    const int lane = tid & 31, grp = lane >> 2, tig = lane & 3;
    float acc[2][8][4] = {};                                  // [mt][nt][4]

    auto compute_stage = [&](int buf) {
        const uint32_t* Au = reinterpret_cast<const uint32_t*>(&As[buf][0][0]);
        const uint32_t* Bu = reinterpret_cast<const uint32_t*>(&Bs[buf][0][0]);
        constexpr int RS = SSTR / 2;                          // 20 uint32 per row
#pragma unroll
        for (int ks = 0; ks < 2; ks++) {
            int kb = ks * 8;                                  // uint32 k-offset
            uint32_t a[2][4];
#pragma unroll
            for (int mt = 0; mt < 2; mt++) {
                int mr = wm * 32 + mt * 16;
                a[mt][0] = Au[(mr + grp    ) * RS + kb + tig    ];
                a[mt][1] = Au[(mr + grp + 8) * RS + kb + tig    ];
                a[mt][2] = Au[(mr + grp    ) * RS + kb + tig + 4];
                a[mt][3] = Au[(mr + grp + 8) * RS + kb + tig + 4];
            }
#pragma unroll
            for (int nt = 0; nt < 8; nt++) {
                int nc = wn * 64 + nt * 8 + grp;              // B row
                uint32_t b0 = Bu[nc * RS + kb + tig    ];
                uint32_t b1 = Bu[nc * RS + kb + tig + 4];
                mma16(acc[0][nt], a[0], b0, b1);
                mma16(acc[1][nt], a[1], b0, b1);
            }
        }
    };

    load_stage(0, 0);
    constexpr int KT = KDIM / BK;
#pragma unroll 1
    for (int kt = 0; kt < KT; ++kt) {
        int cur = kt & 1;
        if (kt + 1 < KT) {
            load_stage(kt + 1, cur ^ 1);
            asm volatile("cp.async.wait_group 1;");
        } else {
            asm volatile("cp.async.wait_group 0;");
        }
        __syncthreads();
        compute_stage(cur);
        __syncthreads();
    }

    // Epilogue
#pragma unroll
    for (int mt = 0; mt < 2; mt++) {
        int rb = wm * 32 + mt * 16 + grp;
#pragma unroll
        for (int half_ = 0; half_ < 2; half_++) {
            int r = m0 + rb + half_ * 8;
            if (r < M) {
                if (MODE == 0 || MODE == 1) {
                    // interleaved (gate, up) pairs -> fused silu -> half hidden
                    __half* dst = (MODE == 0)
                        ? g_hh  + (size_t)(off + r) * ((MODE==0)?HD:HD) // HD
                        : g_hsh + (size_t)r * HSD;
                    int hbase = n0 / 2;
#pragma unroll
                    for (int nt = 0; nt < 8; nt++) {
                        int hcol = hbase + wn * 32 + nt * 4 + tig;
                        float gate = acc[mt][nt][half_*2+0];
                        float up   = acc[mt][nt][half_*2+1];
                        dst[hcol] = __float2half_rn(silu_mul(gate, up));
                    }
                } else {
                    float scale = 1.0f; float* dst;
                    if (MODE == 2) {
                        scale = g_gatew[off + r];
                        dst   = g_yp + (size_t)g_dest[off + r] * CD + n0;
                    } else {
                        dst   = Out + (size_t)r * CD + n0;
                    }
#pragma unroll
                    for (int nt = 0; nt < 8; nt++) {
                        int col = wn * 64 + nt * 8 + tig * 2;
                        float v0 = acc[mt][nt][half_*2+0] * scale;
                        float v1 = acc[mt][nt][half_*2+1] * scale;
                        *reinterpret_cast<float2*>(&dst[col]) = make_float2(v0, v1);
                    }
                }
            }
        }
    }
}

// ---------------------------------------------------------------------------
// Final combine: out[t] += yp[2t] + yp[2t+1]
// ---------------------------------------------------------------------------
__global__ void combine_kernel(float* __restrict__ Out) {
    size_t i = (size_t)blockIdx.x * blockDim.x + threadIdx.x;
    size_t t  = i / (CD / 4);
    size_t c4 = i % (CD / 4);
    float4* o = reinterpret_cast<float4*>(Out) + t * (CD / 4) + c4;
    const float4* p0 = reinterpret_cast<const float4*>(g_yp) + (2 * t) * (CD / 4) + c4;
    const float4* p1 = p0 + (CD / 4);
    float4 a = *o, x0 = *p0, x1 = *p1;
    a.x += x0.x + x1.x; a.y += x0.y + x1.y;
    a.z += x0.z + x1.z; a.w += x0.w + x1.w;
    *o = a;
}

// ---------------------------------------------------------------------------
// Launch — only harness pointers cross the host/device boundary.
// ---------------------------------------------------------------------------
extern "C" void kernel_launch(void* const* d_in, const int* in_sizes, int n_in,
                              void* d_out, int out_size) {
    const float* x   = (const float*)d_in[0];
    const float* Wg  = (const float*)d_in[1];
    const float* W1  = (const float*)d_in[2];
    const float* W2  = (const float*)d_in[3];
    const float* W3  = (const float*)d_in[4];
    const float* Ws1 = (const float*)d_in[5];
    const float* Ws2 = (const float*)d_in[6];
    const float* Ws3 = (const float*)d_in[7];
    float* out = (float*)d_out;

    // routing
    zero_kernel<<<1, 32>>>();
    router_kernel<<<NTOK / 8, 256>>>(x, Wg);
    offsets_kernel<<<1, 32>>>();
    scatter_kernel<<<NTOK / 256, 256>>>();

    // operand conversion
    halfx_kernel<<<(NTOK * CD / 4) / 256, 256>>>(x);

    dim3 tb(32, 8);
    // W1/W2 -> g_w12i interleaved-transposed: [e][2c+p][k]
    transpose_half_kernel<0, 2, 0><<<dim3(HD / 32, CD / 32, NE), tb>>>(
        W1, CD, HD, (size_t)CD * HD, (size_t)(2*HD) * CD);
    transpose_half_kernel<0, 2, 1><<<dim3(HD / 32, CD / 32, NE), tb>>>(
        W2, CD, HD, (size_t)CD * HD, (size_t)(2*HD) * CD);
    // Ws1/Ws2 -> g_ws12
    transpose_half_kernel<1, 2, 0><<<dim3(HSD / 32, CD / 32, 1), tb>>>(
        Ws1, CD, HSD, 0, 0);
    transpose_half_kernel<1, 2, 1><<<dim3(HSD / 32, CD / 32, 1), tb>>>(
        Ws2, CD, HSD, 0, 0);
    // W3 -> g_w3t [e][n][k]
    transpose_half_kernel<2, 1, 0><<<dim3(CD / 32, HD / 32, NE), tb>>>(
        W3, HD, CD, (size_t)HD * CD, (size_t)CD * HD);
    // Ws3 -> g_ws3t
    transpose_half_kernel<3, 1, 0><<<dim3(CD / 32, HSD / 32, 1), tb>>>(
        Ws3, HSD, CD, 0, 0);

    // stage 1 GEMMs (fused silu epilogue)
    gemm_fp16<CD, 2*HD,  0><<<dim3(2*HD  / BN, NTOK / BM, NE), NTHR>>>(out);
    gemm_fp16<CD, 2*HSD, 1><<<dim3(2*HSD / BN, NTOK / BM, 1),  NTHR>>>(out);

    // stage 2 GEMMs
    gemm_fp16<HSD, CD, 3><<<dim3(CD / BN, NTOK / BM, 1),  NTHR>>>(out);
    gemm_fp16<HD,  CD, 2><<<dim3(CD / BN, NTOK / BM, NE), NTHR>>>(out);

    // combine
    combine_kernel<<<(NTOK * CD / 4) / 256, 256>>>(out);
}

// round 15
// speedup vs baseline: 1.7633x; 1.0076x over previous
#include <cuda_runtime.h>
#include <cuda_fp16.h>
#include <cstdint>
#include <math.h>

// ---------------------------------------------------------------------------
// Problem constants
// ---------------------------------------------------------------------------
namespace {
constexpr int NTOK = 8192;      // B*T
constexpr int CD   = 1024;      // C
constexpr int NE   = 8;
constexpr int HD   = 1408;
constexpr int HSD  = 2816;
constexpr int NPAIR = NTOK * 2;

// GEMM tiling: fp16 m16n8k16, BK=32 (2 k-steps)
constexpr int BM = 128, BN = 128, BK = 32, NTHR = 256;
constexpr int SPAD = 8;                     // halves of row padding
constexpr int SSTR = BK + SPAD;             // 40 halves (80 B row stride)
constexpr int STAGE_B = BM * SSTR * 2;      // 10240 B per A/B stage
}

// ---------------------------------------------------------------------------
// Scratch (allocation-free __device__ globals; referenced ONLY in device code)
// ---------------------------------------------------------------------------
__device__ int    g_counts[NE];
__device__ int    g_offsets[NE];
__device__ int    g_cursor[NE];
__device__ int    g_tok[NPAIR];
__device__ float  g_gatew[NPAIR];
__device__ int    g_dest[NPAIR];
__device__ int    g_topi[NPAIR];
__device__ float  g_topp[NPAIR];

__device__ __half g_xh  [(size_t)NTOK * CD];          // half x
__device__ __half g_w12i[(size_t)NE * (2*HD) * CD];   // [e][2c+{0,1}][k]: interleaved W1/W2, transposed
__device__ __half g_ws12[(size_t)(2*HSD) * CD];       // interleaved Ws1/Ws2, transposed
__device__ __half g_w3t [(size_t)NE * CD * HD];       // W3 transposed [n][k]
__device__ __half g_ws3t[(size_t)CD * HSD];           // Ws3 transposed
__device__ __half g_hh  [(size_t)NPAIR * HD];         // gated expert hidden (half)
__device__ __half g_hsh [(size_t)NTOK * HSD];         // gated shared hidden (half)
__device__ float  g_yp  [(size_t)NPAIR * CD];         // per-pair expert outputs (fp32)

// ---------------------------------------------------------------------------
// Helpers
// ---------------------------------------------------------------------------
__device__ __forceinline__ float silu_mul(float g, float u) {
    return (g / (1.0f + expf(-g))) * u;
}
__device__ __forceinline__ void mma16(float d[4], const uint32_t a[4],
                                      uint32_t b0, uint32_t b1) {
    asm volatile(
        "mma.sync.aligned.m16n8k16.row.col.f32.f16.f16.f32 "
        "{%0,%1,%2,%3},{%4,%5,%6,%7},{%8,%9},{%0,%1,%2,%3};"
        : "+f"(d[0]), "+f"(d[1]), "+f"(d[2]), "+f"(d[3])
        : "r"(a[0]), "r"(a[1]), "r"(a[2]), "r"(a[3]), "r"(b0), "r"(b1));
}
__device__ __forceinline__ void cp16h(__half* smem_dst, const __half* gsrc) {
    uint32_t s = (uint32_t)__cvta_generic_to_shared(smem_dst);
    asm volatile("cp.async.cg.shared.global [%0], [%1], 16;" :: "r"(s), "l"(gsrc));
}
__device__ __forceinline__ void ldm4(uint32_t& r0, uint32_t& r1,
                                     uint32_t& r2, uint32_t& r3, uint32_t addr) {
    asm volatile("ldmatrix.sync.aligned.m8n8.x4.shared.b16 {%0,%1,%2,%3}, [%4];"
                 : "=r"(r0), "=r"(r1), "=r"(r2), "=r"(r3) : "r"(addr));
}

// ---------------------------------------------------------------------------
// Router / routing bookkeeping (proven code)
// ---------------------------------------------------------------------------
__global__ void router_kernel(const float* __restrict__ x,
                              const float* __restrict__ Wg) {
    int warp = threadIdx.x >> 5, lane = threadIdx.x & 31;
    int t = blockIdx.x * 8 + warp;
    const float* xr = x + (size_t)t * CD;
    float acc[NE];
#pragma unroll
    for (int e = 0; e < NE; e++) acc[e] = 0.f;
    for (int c = lane; c < CD; c += 32) {
        float xv = __ldg(xr + c);
        const float4* wr = reinterpret_cast<const float4*>(Wg + c * NE);
        float4 w0 = wr[0], w1 = wr[1];
        acc[0] += xv * w0.x; acc[1] += xv * w0.y;
        acc[2] += xv * w0.z; acc[3] += xv * w0.w;
        acc[4] += xv * w1.x; acc[5] += xv * w1.y;
        acc[6] += xv * w1.z; acc[7] += xv * w1.w;
    }
#pragma unroll
    for (int off = 16; off > 0; off >>= 1)
#pragma unroll
        for (int e = 0; e < NE; e++)
            acc[e] += __shfl_xor_sync(0xffffffffu, acc[e], off);

    if (lane == 0) {
        int i0 = 0; float l0 = acc[0];
#pragma unroll
        for (int e = 1; e < NE; e++) if (acc[e] > l0) { l0 = acc[e]; i0 = e; }
        int i1 = (i0 == 0) ? 1 : 0; float l1 = acc[i1];
#pragma unroll
        for (int e = 0; e < NE; e++)
            if (e != i0 && acc[e] > l1) { l1 = acc[e]; i1 = e; }
        float ex = expf(l1 - l0);
        float inv = 1.0f / (1.0f + ex);
        g_topi[2*t]   = i0;  g_topi[2*t+1] = i1;
        g_topp[2*t]   = inv; g_topp[2*t+1] = ex * inv;
        atomicAdd(&g_counts[i0], 1);
        atomicAdd(&g_counts[i1], 1);
    }
}

__global__ void zero_kernel() {
    if (threadIdx.x < NE) g_counts[threadIdx.x] = 0;
}
__global__ void offsets_kernel() {
    if (threadIdx.x == 0) {
        int s = 0;
        for (int e = 0; e < NE; e++) { g_offsets[e] = s; g_cursor[e] = s; s += g_counts[e]; }
    }
}
__global__ void scatter_kernel() {
    int t = blockIdx.x * blockDim.x + threadIdx.x;
    if (t < NTOK) {
#pragma unroll
        for (int k = 0; k < 2; k++) {
            int e = g_topi[2*t + k];
            int pos = atomicAdd(&g_cursor[e], 1);
            g_tok[pos]   = t;
            g_gatew[pos] = g_topp[2*t + k];
            g_dest[pos]  = 2*t + k;
        }
    }
}

// ---------------------------------------------------------------------------
// x -> half
// ---------------------------------------------------------------------------
__global__ void halfx_kernel(const float* __restrict__ x) {
    size_t i = (size_t)blockIdx.x * blockDim.x + threadIdx.x;   // over N*C/4
    float4 v = reinterpret_cast<const float4*>(x)[i];
    __half2* d = reinterpret_cast<__half2*>(g_xh) + i * 2;
    d[0] = __floats2half2_rn(v.x, v.y);
    d[1] = __floats2half2_rn(v.z, v.w);
}

// ---------------------------------------------------------------------------
// Transpose + convert: src [z][R][C] fp32 -> dst rows oc = c*OS + OO, dst[z][oc][R] half
// DSTID: 0 g_w12i, 1 g_ws12, 2 g_w3t, 3 g_ws3t
// ---------------------------------------------------------------------------
template<int DSTID, int OS, int OO>
__global__ void transpose_half_kernel(const float* __restrict__ src,
                                      int R, int C,
                                      size_t in_bstride, size_t out_bstride) {
    __shared__ float t[32][33];
    __half* dstb = (DSTID == 0) ? g_w12i
                 : (DSTID == 1) ? g_ws12
                 : (DSTID == 2) ? g_w3t
                                : g_ws3t;
    const float* ip = src + (size_t)blockIdx.z * in_bstride;
    __half* op = dstb + (size_t)blockIdx.z * out_bstride;
    int c0 = blockIdx.x * 32, r0 = blockIdx.y * 32;
    int tx = threadIdx.x, ty = threadIdx.y;
#pragma unroll
    for (int j = 0; j < 4; j++)
        t[ty + 8*j][tx] = ip[(size_t)(r0 + ty + 8*j) * C + c0 + tx];
    __syncthreads();
#pragma unroll
    for (int j = 0; j < 4; j++) {
        int oc = (c0 + ty + 8*j) * OS + OO;
        op[(size_t)oc * R + r0 + tx] = __float2half_rn(t[tx][ty + 8*j]);
    }
}

// ---------------------------------------------------------------------------
// Unified fp16 GEMM with ldmatrix fragment feeding.
// MODE 0: A = g_xh gathered via g_tok, B = g_w12i[e] -> silu-fused -> g_hh
// MODE 1: A = g_xh direct,             B = g_ws12    -> silu-fused -> g_hsh
// MODE 2: A = g_hh grouped,            B = g_w3t[e]  -> g_yp (gate-scaled)
// MODE 3: A = g_hsh direct,            B = g_ws3t    -> Out
// BM=128, BN=128 (B rows), BK=32, 256 thr, 8 warps (4m x 2n), warptile 32x64.
// ---------------------------------------------------------------------------
template<int KDIM, int NROWS, int MODE>
__global__ __launch_bounds__(NTHR)
void gemm_fp16(float* __restrict__ Out) {
    __shared__ __align__(16) __half As[2][BM][SSTR];
    __shared__ __align__(16) __half Bs[2][BN][SSTR];

    const __half* Bt = (MODE == 0) ? g_w12i
                     : (MODE == 1) ? g_ws12
                     : (MODE == 2) ? g_w3t
                                   : g_ws3t;

    const int e   = (MODE == 0 || MODE == 2) ? blockIdx.z : 0;
    const int M   = (MODE == 0 || MODE == 2) ? g_counts[e]  : NTOK;
    const int off = (MODE == 0 || MODE == 2) ? g_offsets[e] : 0;
    const int m0  = blockIdx.y * BM;
    if (m0 >= M) return;
    const int n0  = blockIdx.x * BN;

    const __half* B = Bt + (size_t)e * NROWS * KDIM;
    const int tid = threadIdx.x;

    // A loader: 128 rows x 4 chunks(16B=8 halves) = 512 chunks -> 2/thread
    int ar[2], ac8[2]; const __half* ap[2];
#pragma unroll
    for (int j = 0; j < 2; j++) {
        int chunk = tid + j * NTHR;
        ar[j]  = chunk >> 2;                   // 0..127
        ac8[j] = (chunk & 3) * 8;              // {0,8,16,24}
        int rr = m0 + ar[j]; if (rr >= M) rr = M - 1;
        if (MODE == 0)      ap[j] = g_xh + (size_t)g_tok[off + rr] * KDIM + ac8[j];
        else if (MODE == 1) ap[j] = g_xh + (size_t)rr * KDIM + ac8[j];
        else if (MODE == 2) ap[j] = g_hh + (size_t)(off + rr) * KDIM + ac8[j];
        else                ap[j] = g_hsh + (size_t)rr * KDIM + ac8[j];
    }
    // B loader: 128 B-rows x 4 chunks -> 512 chunks -> 2/thread
    int brr[2], bc8[2]; const __half* bp[2];
#pragma unroll
    for (int j = 0; j < 2; j++) {
        int chunk = tid + j * NTHR;
        brr[j] = chunk >> 2;
        bc8[j] = (chunk & 3) * 8;
        bp[j]  = B + (size_t)(n0 + brr[j]) * KDIM + bc8[j];
    }

    auto load_stage = [&](int kt, int buf) {
        int k0 = kt * BK;
#pragma unroll
        for (int j = 0; j < 2; j++)
            cp16h(&As[buf][ar[j]][ac8[j]], ap[j] + k0);
#pragma unroll
        for (int j = 0; j < 2; j++)
            cp16h(&Bs[buf][brr[j]][bc8[j]], bp[j] + k0);
        asm volatile("cp.async.commit_group;");
    };

    const int wid = tid >> 5, wm = wid & 3, wn = wid >> 2;   // 4m x 2n warps
    const int lane = tid & 31, grp = lane >> 2, tig = lane & 3;
    float acc[2][8][4] = {};                                  // [mt][nt][4]

    // ldmatrix per-thread base addresses (bytes, shared space)
    // A x4 tile order: (m0-7,k0-7),(m8-15,k0-7),(m0-7,k8-15),(m8-15,k8-15)
    //   rows t0-15 -> m + (lane&15); t16-31 same rows at +16B k-offset
    const uint32_t asb = (uint32_t)__cvta_generic_to_shared(&As[0][0][0]);
    const uint32_t bsb = (uint32_t)__cvta_generic_to_shared(&Bs[0][0][0]);
    const uint32_t aAddr = asb
        + (uint32_t)((wm * 32 + (lane & 15)) * SSTR) * 2
        + (uint32_t)(lane >> 4) * 16;
    // B x4 tile order: b0(nt), b1(nt), b0(nt+1), b1(nt+1)
    //   t0-7: nt rows k0; t8-15: nt rows k+16B; t16-23: nt+1 rows k0; t24-31: nt+1 rows k+16B
    const uint32_t bAddr = bsb
        + (uint32_t)((wn * 64 + (lane & 7) + ((lane >> 4) << 3)) * SSTR) * 2
        + (uint32_t)((lane >> 3) & 1) * 16;

    auto compute_stage = [&](int buf) {
        uint32_t ab = aAddr + buf * STAGE_B;
        uint32_t bb = bAddr + buf * STAGE_B;
#pragma unroll
        for (int ks = 0; ks < 2; ks++) {
            uint32_t koff = ks * 32;                 // 16 halves
            uint32_t a[2][4];
            ldm4(a[0][0], a[0][1], a[0][2], a[0][3], ab + koff);
            ldm4(a[1][0], a[1][1], a[1][2], a[1][3], ab + 16 * SSTR * 2 + koff);
            uint32_t b[8][2];
#pragma unroll
            for (int np = 0; np < 4; np++)
                ldm4(b[2*np][0], b[2*np][1], b[2*np+1][0], b[2*np+1][1],
                     bb + np * 16 * SSTR * 2 + koff);
#pragma unroll
            for (int nt = 0; nt < 8; nt++) {
                mma16(acc[0][nt], a[0], b[nt][0], b[nt][1]);
                mma16(acc[1][nt], a[1], b[nt][0], b[nt][1]);
            }
        }
    };

    load_stage(0, 0);
    constexpr int KT = KDIM / BK;
#pragma unroll 1
    for (int kt = 0; kt < KT; ++kt) {
        int cur = kt & 1;
        if (kt + 1 < KT) {
            load_stage(kt + 1, cur ^ 1);
            asm volatile("cp.async.wait_group 1;");
        } else {
            asm volatile("cp.async.wait_group 0;");
        }
        __syncthreads();
        compute_stage(cur);
        __syncthreads();
    }

    // Epilogue
#pragma unroll
    for (int mt = 0; mt < 2; mt++) {
        int rb = wm * 32 + mt * 16 + grp;
#pragma unroll
        for (int half_ = 0; half_ < 2; half_++) {
            int r = m0 + rb + half_ * 8;
            if (r < M) {
                if (MODE == 0 || MODE == 1) {
                    // interleaved (gate, up) pairs -> fused silu -> half hidden
                    __half* dst = (MODE == 0)
                        ? g_hh  + (size_t)(off + r) * HD
                        : g_hsh + (size_t)r * HSD;
                    int hbase = n0 / 2;
#pragma unroll
                    for (int nt = 0; nt < 8; nt++) {
                        int hcol = hbase + wn * 32 + nt * 4 + tig;
                        float gate = acc[mt][nt][half_*2+0];
                        float up   = acc[mt][nt][half_*2+1];
                        dst[hcol] = __float2half_rn(silu_mul(gate, up));
                    }
                } else {
                    float scale = 1.0f; float* dst;
                    if (MODE == 2) {
                        scale = g_gatew[off + r];
                        dst   = g_yp + (size_t)g_dest[off + r] * CD + n0;
                    } else {
                        dst   = Out + (size_t)r * CD + n0;
                    }
#pragma unroll
                    for (int nt = 0; nt < 8; nt++) {
                        int col = wn * 64 + nt * 8 + tig * 2;
                        float v0 = acc[mt][nt][half_*2+0] * scale;
                        float v1 = acc[mt][nt][half_*2+1] * scale;
                        *reinterpret_cast<float2*>(&dst[col]) = make_float2(v0, v1);
                    }
                }
            }
        }
    }
}

// ---------------------------------------------------------------------------
// Final combine: out[t] += yp[2t] + yp[2t+1]
// ---------------------------------------------------------------------------
__global__ void combine_kernel(float* __restrict__ Out) {
    size_t i = (size_t)blockIdx.x * blockDim.x + threadIdx.x;
    size_t t  = i / (CD / 4);
    size_t c4 = i % (CD / 4);
    float4* o = reinterpret_cast<float4*>(Out) + t * (CD / 4) + c4;
    const float4* p0 = reinterpret_cast<const float4*>(g_yp) + (2 * t) * (CD / 4) + c4;
    const float4* p1 = p0 + (CD / 4);
    float4 a = *o, x0 = *p0, x1 = *p1;
    a.x += x0.x + x1.x; a.y += x0.y + x1.y;
    a.z += x0.z + x1.z; a.w += x0.w + x1.w;
    *o = a;
}

// ---------------------------------------------------------------------------
// Launch — only harness pointers cross the host/device boundary.
// ---------------------------------------------------------------------------
extern "C" void kernel_launch(void* const* d_in, const int* in_sizes, int n_in,
                              void* d_out, int out_size) {
    const float* x   = (const float*)d_in[0];
    const float* Wg  = (const float*)d_in[1];
    const float* W1  = (const float*)d_in[2];
    const float* W2  = (const float*)d_in[3];
    const float* W3  = (const float*)d_in[4];
    const float* Ws1 = (const float*)d_in[5];
    const float* Ws2 = (const float*)d_in[6];
    const float* Ws3 = (const float*)d_in[7];
    float* out = (float*)d_out;

    // routing
    zero_kernel<<<1, 32>>>();
    router_kernel<<<NTOK / 8, 256>>>(x, Wg);
    offsets_kernel<<<1, 32>>>();
    scatter_kernel<<<NTOK / 256, 256>>>();

    // operand conversion
    halfx_kernel<<<(NTOK * CD / 4) / 256, 256>>>(x);

    dim3 tb(32, 8);
    // W1/W2 -> g_w12i interleaved-transposed: [e][2c+p][k]
    transpose_half_kernel<0, 2, 0><<<dim3(HD / 32, CD / 32, NE), tb>>>(
        W1, CD, HD, (size_t)CD * HD, (size_t)(2*HD) * CD);
    transpose_half_kernel<0, 2, 1><<<dim3(HD / 32, CD / 32, NE), tb>>>(
        W2, CD, HD, (size_t)CD * HD, (size_t)(2*HD) * CD);
    // Ws1/Ws2 -> g_ws12
    transpose_half_kernel<1, 2, 0><<<dim3(HSD / 32, CD / 32, 1), tb>>>(
        Ws1, CD, HSD, 0, 0);
    transpose_half_kernel<1, 2, 1><<<dim3(HSD / 32, CD / 32, 1), tb>>>(
        Ws2, CD, HSD, 0, 0);
    // W3 -> g_w3t [e][n][k]
    transpose_half_kernel<2, 1, 0><<<dim3(CD / 32, HD / 32, NE), tb>>>(
        W3, HD, CD, (size_t)HD * CD, (size_t)CD * HD);
    // Ws3 -> g_ws3t
    transpose_half_kernel<3, 1, 0><<<dim3(CD / 32, HSD / 32, 1), tb>>>(
        Ws3, HSD, CD, 0, 0);

    // stage 1 GEMMs (fused silu epilogue)
    gemm_fp16<CD, 2*HD,  0><<<dim3(2*HD  / BN, NTOK / BM, NE), NTHR>>>(out);
    gemm_fp16<CD, 2*HSD, 1><<<dim3(2*HSD / BN, NTOK / BM, 1),  NTHR>>>(out);

    // stage 2 GEMMs
    gemm_fp16<HSD, CD, 3><<<dim3(CD / BN, NTOK / BM, 1),  NTHR>>>(out);
    gemm_fp16<HD,  CD, 2><<<dim3(CD / BN, NTOK / BM, NE), NTHR>>>(out);

    // combine
    combine_kernel<<<(NTOK * CD / 4) / 256, 256>>>(out);
}